// round 6
// baseline (speedup 1.0000x reference)
#include <cuda_runtime.h>

// q,k,v,out: (B=4, S=4096, H=16, D=64) f32. Hilbert gather/scatter cancel
// (attention is strictly per-position), leaving per-(b,s) 8x8 head-vs-head
// attention in two head groups of 8, inner dim 64.
//
// R4b (resubmit after infra failure): warp = (position, group). Lane l owns
// dims {2l, 2l+1} of ALL 8 heads. Gram matrix computed locally (no shuffles),
// summed across lanes via butterfly reduce-scatter (62 shfl), softmax in
// 4-lane groups, butterfly allgather of weights (62 shfl), AV local.
// 128 shuffles/warp vs 272 in R3.
#define NPOS  16384
#define SCALE 0.125f

__global__ __launch_bounds__(256)
void hilbert_headattn_kernel(const float2* __restrict__ q,
                             const float2* __restrict__ k,
                             const float2* __restrict__ v,
                             float2* __restrict__ out)
{
    const int lane = threadIdx.x & 31;
    const int wid  = blockIdx.x * 8 + (threadIdx.x >> 5);
    const int pos  = wid >> 1;
    const int g    = wid & 1;

    // float2 index of this lane's dim-pair in head 0 of its group
    const int base2 = pos * 512 + g * 256 + lane;

    float qr[16], kr[16], vr[16];
#pragma unroll
    for (int i = 0; i < 8; i++) {
        float2 t;
        t = q[base2 + i * 32]; qr[2*i] = t.x * SCALE; qr[2*i+1] = t.y * SCALE;
        t = k[base2 + i * 32]; kr[2*i] = t.x;         kr[2*i+1] = t.y;
        t = v[base2 + i * 32]; vr[2*i] = t.x;         vr[2*i+1] = t.y;
    }

    // ---- local partial Gram over this lane's 2 dims: P[i*8+j] ----
    float P[64];
#pragma unroll
    for (int i = 0; i < 8; i++)
#pragma unroll
        for (int j = 0; j < 8; j++)
            P[i*8+j] = fmaf(qr[2*i], kr[2*j], qr[2*i+1] * kr[2*j+1]);

    // ---- butterfly reduce-scatter over 32 lanes (5 stages) ----
    // Invariant: after stage s (mask 16>>s), element bit (5-s) == lane bit (4-s).
    // Final: lane l holds entries x = 2l+{0,1} -> row i=l>>2, col j=2*(l&3)+t.
#pragma unroll
    for (int s = 0; s < 5; s++) {
        const int  m    = 16 >> s;
        const int  half = 32 >> s;
        const bool b    = (lane & m) != 0;
#pragma unroll
        for (int t = 0; t < half; t++) {
            const float snd  = b ? P[t]        : P[t + half];
            const float kept = b ? P[t + half] : P[t];
            P[t] = kept + __shfl_xor_sync(0xffffffffu, snd, m);
        }
    }

    // ---- softmax over j (row i spread across 4 aligned lanes, 2 cols each) ----
    float s0 = P[0], s1 = P[1];
    float mx = fmaxf(s0, s1);
    mx = fmaxf(mx, __shfl_xor_sync(0xffffffffu, mx, 1));
    mx = fmaxf(mx, __shfl_xor_sync(0xffffffffu, mx, 2));
    const float e0 = __expf(s0 - mx), e1 = __expf(s1 - mx);
    float sm = e0 + e1;
    sm += __shfl_xor_sync(0xffffffffu, sm, 1);
    sm += __shfl_xor_sync(0xffffffffu, sm, 2);
    const float inv = __frcp_rn(sm);

    float A[64];
    A[0] = e0 * inv;
    A[1] = e1 * inv;

    // ---- butterfly allgather of the 64 weights (5 stages, reverse order) ----
    // Invariant: after stage s, lane holds elements 2^(s+2)*(l>>(s+1)) + [0, 2^(s+2)).
#pragma unroll
    for (int s = 0; s < 5; s++) {
        const int  m = 1 << s;
        const int  B = 2 << s;
        const bool b = (lane & m) != 0;
#pragma unroll
        for (int t = 0; t < B; t++) {
            const float r  = __shfl_xor_sync(0xffffffffu, A[t], m);
            const float lo = b ? r    : A[t];
            const float hi = b ? A[t] : r;
            A[t]     = lo;
            A[t + B] = hi;
        }
    }
    // A[i*8+j] now complete in every lane.

    // ---- AV: out[i, lane dims] = sum_j A[i,j] * v[j, lane dims] ----
#pragma unroll
    for (int i = 0; i < 8; i++) {
        float o0 = 0.f, o1 = 0.f;
#pragma unroll
        for (int j = 0; j < 8; j++) {
            const float a = A[i*8+j];
            o0 = fmaf(a, vr[2*j],   o0);
            o1 = fmaf(a, vr[2*j+1], o1);
        }
        out[base2 + i * 32] = make_float2(o0, o1);
    }
}

extern "C" void kernel_launch(void* const* d_in, const int* in_sizes, int n_in,
                              void* d_out, int out_size)
{
    const float2* q = (const float2*)d_in[0];
    const float2* k = (const float2*)d_in[1];
    const float2* v = (const float2*)d_in[2];
    float2* o       = (float2*)d_out;
    // 256 threads = 8 warps; 2 warps (groups) per position; 4 positions per CTA
    hilbert_headattn_kernel<<<NPOS / 4, 256>>>(q, k, v, o);
}